// round 15
// baseline (speedup 1.0000x reference)
#include <cuda_runtime.h>
#include <cuda_bf16.h>

#define NP 9216      // H*W
#define C  256
#define CO 32        // C/8
#define L2E 1.4426950408889634f
#define NPH 4608     // NP/2 (u32 pairs per row)

typedef unsigned long long ull;
typedef unsigned int u32;

// ---------------- device scratch (static; no dynamic allocation) -----------
__device__ __nv_bfloat16 g_Yt[(size_t)NP * 64]; // [i][o]: 0..31 hi, 32..63 lo
__device__ float g_Zp[4][NP];
__device__ u32   g_Wh[(size_t)NP * NPH];        // W = exp(S - M/2), bf16 pairs [j][i]
__device__ u32   g_Vh[(size_t)C * NPH];         // V' = x*invZ, bf16 pairs [c][i]
__device__ float g_Pt[(size_t)C * NP];          // P [c][j]
__device__ float g_k4m[C][9];
__device__ float g_k4s[C][9];
__device__ float g_cmax[C];
__device__ float g_cisum[C];
__device__ int   g_Mbits;

// ---------------- PTX helpers ----------------------------------------------
__device__ __forceinline__ u32 s2u(const void* p) {
    u32 a;
    asm("{ .reg .u64 t; cvta.to.shared.u64 t, %1; cvt.u32.u64 %0, t; }"
        : "=r"(a) : "l"(p));
    return a;
}
__device__ __forceinline__ void mmab(float* d, const u32* a, const u32* b) {
    asm volatile(
        "mma.sync.aligned.m16n8k16.row.col.f32.bf16.bf16.f32 "
        "{%0,%1,%2,%3}, {%4,%5,%6,%7}, {%8,%9}, {%0,%1,%2,%3};"
        : "+f"(d[0]), "+f"(d[1]), "+f"(d[2]), "+f"(d[3])
        : "r"(a[0]), "r"(a[1]), "r"(a[2]), "r"(a[3]), "r"(b[0]), "r"(b[1]));
}
__device__ __forceinline__ void ldmx4(u32* r, u32 addr) {
    asm volatile("ldmatrix.sync.aligned.m8n8.x4.shared.b16 {%0,%1,%2,%3}, [%4];"
                 : "=r"(r[0]), "=r"(r[1]), "=r"(r[2]), "=r"(r[3]) : "r"(addr));
}
#define CPA16(s, g) asm volatile("cp.async.cg.shared.global [%0], [%1], 16;" :: "r"(s), "l"(g))
#define CPCOMMIT()  asm volatile("cp.async.commit_group;" ::: "memory")
#define CPWAIT0()   asm volatile("cp.async.wait_group 0;" ::: "memory")
#define CPWAIT1()   asm volatile("cp.async.wait_group 1;" ::: "memory")

// ---------------- k0 --------------------------------------------------------
__global__ void k0_init() { if (threadIdx.x == 0) g_Mbits = 0; }

// ---------------- k1: conv -> Yt (bf16 hi/lo, i = w*96+h), M ---------------
__global__ void __launch_bounds__(128) k1_conv(const float* __restrict__ x,
                                               const float* __restrict__ wc,
                                               const float* __restrict__ bc) {
    __shared__ float ws[C * CO];
    __shared__ float bs[CO];
    int t = threadIdx.x;
    for (int idx = t; idx < C * CO; idx += 128)
        ws[idx] = wc[(idx & 31) * C + (idx >> 5)];
    if (t < CO) bs[t] = bc[t];
    __syncthreads();

    int pos = blockIdx.x * 128 + t;                  // h*96 + w
    float acc[CO];
#pragma unroll
    for (int o = 0; o < CO; o++) acc[o] = bs[o];
#pragma unroll 4
    for (int c = 0; c < C; c++) {
        float xv = x[c * NP + pos];
        const float4* wp = (const float4*)&ws[c * CO];
#pragma unroll
        for (int q = 0; q < 8; q++) {
            float4 w4 = wp[q];
            acc[q * 4 + 0] += w4.x * xv;
            acc[q * 4 + 1] += w4.y * xv;
            acc[q * 4 + 2] += w4.z * xv;
            acc[q * 4 + 3] += w4.w * xv;
        }
    }
    int h = pos / 96, w = pos - h * 96;
    int i = w * 96 + h;                              // transposed spatial index
    float ss = 0.0f;
#pragma unroll
    for (int o = 0; o < CO; o++) {
        float a = acc[o];
        ss += a * a;
        __nv_bfloat16 hb = __float2bfloat16(a);
        g_Yt[(size_t)i * 64 + o] = hb;
        g_Yt[(size_t)i * 64 + 32 + o] = __float2bfloat16(a - __bfloat162float(hb));
    }
    atomicMax(&g_Mbits, __float_as_int(ss));
}

// ---------------- kS: S tiles (mma 3-term), W = exp2(S*l2e - M/2*l2e) ------
// grid (72, 4): j-tile 128, i-quarter of 18 i-tiles (128 each). 256 thr, 2/SM.
// dyn smem: A[0,18432) B0[18432,36864) B1[36864,55296)
__global__ void __launch_bounds__(256, 2) kS() {
    extern __shared__ __align__(16) char dsm[];
    int t = threadIdx.x, lane = t & 31, wid = t >> 5;
    int j0 = blockIdx.x * 128, q = blockIdx.y;
    u32 aB = s2u(dsm);
    float mh = 0.5f * __int_as_float(g_Mbits) * L2E;

    // stage A (j-tile) + B(0) in one group
#pragma unroll
    for (int k = 0; k < 4; k++) {
        int idx = t + k * 256;
        int row = idx >> 3, g = idx & 7;
        CPA16(aB + row * 144 + g * 16,
              (const char*)g_Yt + (size_t)(j0 + row) * 128 + g * 16);
    }
    int ib0 = q * 2304;
#pragma unroll
    for (int k = 0; k < 4; k++) {
        int idx = t + k * 256;
        int row = idx >> 3, g = idx & 7;
        CPA16(aB + 18432 + row * 144 + g * 16,
              (const char*)g_Yt + (size_t)(ib0 + row) * 128 + g * 16);
    }
    CPCOMMIT();
    CPWAIT0();
    __syncthreads();

    // A fragments, resident in regs
    u32 af[4][4];
    {
        int arow = wid * 16 + (lane & 7) + ((lane >> 3) & 1) * 8;
        int abo = (lane >> 4) * 16;
#pragma unroll
        for (int kc = 0; kc < 4; kc++)
            ldmx4(af[kc], aB + arow * 144 + kc * 32 + abo);
    }

    int r0 = wid * 16 + (lane >> 2), r1 = r0 + 8;
    float z0 = 0.f, z1 = 0.f;

    for (int it = 0; it < 18; it++) {
        if (it + 1 < 18) {
            int i1 = q * 2304 + (it + 1) * 128;
            u32 st = aB + 18432 + ((it + 1) & 1) * 18432;
#pragma unroll
            for (int k = 0; k < 4; k++) {
                int idx = t + k * 256;
                int row = idx >> 3, g = idx & 7;
                CPA16(st + row * 144 + g * 16,
                      (const char*)g_Yt + (size_t)(i1 + row) * 128 + g * 16);
            }
            CPCOMMIT();
            CPWAIT1();
        } else {
            CPWAIT0();
        }
        __syncthreads();

        u32 bB = aB + 18432 + (it & 1) * 18432;
        int i0 = q * 2304 + it * 128;

        float acc[16][4];
#pragma unroll
        for (int n = 0; n < 16; n++)
#pragma unroll
            for (int r = 0; r < 4; r++) acc[n][r] = 0.f;

#pragma unroll
        for (int n = 0; n < 16; n++) {
            u32 bh[4], bl[4];
            int brow = n * 8 + (lane & 7);
            int bbo = (lane >> 3) * 16;
            ldmx4(bh, bB + brow * 144 + bbo);
            ldmx4(bl, bB + brow * 144 + 64 + bbo);
            mmab(acc[n], af[0], &bh[0]);             // hh
            mmab(acc[n], af[1], &bh[2]);
            mmab(acc[n], af[0], &bl[0]);             // hl
            mmab(acc[n], af[1], &bl[2]);
            mmab(acc[n], af[2], &bh[0]);             // lh
            mmab(acc[n], af[3], &bh[2]);
        }

        // epilogue: t = exp2(S*l2e - mh); z += t; store bf16 W
#pragma unroll
        for (int n = 0; n < 16; n++) {
            int cc = n * 8 + 2 * (lane & 3);
            float t0 = exp2f(fmaf(acc[n][0], L2E, -mh));
            float t1 = exp2f(fmaf(acc[n][1], L2E, -mh));
            float t2 = exp2f(fmaf(acc[n][2], L2E, -mh));
            float t3 = exp2f(fmaf(acc[n][3], L2E, -mh));
            z0 += t0 + t1;
            z1 += t2 + t3;
            __nv_bfloat162 h0 = __floats2bfloat162_rn(t0, t1);
            __nv_bfloat162 h1 = __floats2bfloat162_rn(t2, t3);
            size_t ip = (size_t)(i0 + cc) >> 1;
            g_Wh[(size_t)(j0 + r0) * NPH + ip] = *(u32*)&h0;
            g_Wh[(size_t)(j0 + r1) * NPH + ip] = *(u32*)&h1;
        }
        __syncthreads();
    }
    z0 += __shfl_xor_sync(~0u, z0, 1); z0 += __shfl_xor_sync(~0u, z0, 2);
    z1 += __shfl_xor_sync(~0u, z1, 1); z1 += __shfl_xor_sync(~0u, z1, 2);
    if ((lane & 3) == 0) {
        g_Zp[q][j0 + r0] = z0;
        g_Zp[q][j0 + r1] = z1;
    }
}

// ---------------- kV: V'[c][i] = x[c][i]/Z[i], bf16 (invZ inline) -----------
__global__ void __launch_bounds__(256) kV(const float* __restrict__ x) {
    int c = blockIdx.y;
    int i = blockIdx.x * 256 + threadIdx.x;          // pair index < 4608
    float2 xv = *(const float2*)&x[(size_t)c * NP + 2 * i];
    float z0 = ((g_Zp[0][2 * i] + g_Zp[1][2 * i]) + g_Zp[2][2 * i]) + g_Zp[3][2 * i];
    float z1 = ((g_Zp[0][2 * i + 1] + g_Zp[1][2 * i + 1]) + g_Zp[2][2 * i + 1]) + g_Zp[3][2 * i + 1];
    __nv_bfloat162 hh = __floats2bfloat162_rn(xv.x / z0, xv.y / z1);
    g_Vh[(size_t)c * NPH + i] = *(u32*)&hh;
}

// ---------------- kPV: Pt[c][j] = sum_i V'[c][i]*W[j][i], single-term -------
// grid (144): j-tile 64, m = all 256 c. 256 thr, 2 blocks/SM. K-chunk 32.
// dyn smem stage (25600): Vh[0,20480) Wh[20480,25600); x2 = 51200
__global__ void __launch_bounds__(256, 2) kPV() {
    extern __shared__ __align__(16) char dsm[];
    int t = threadIdx.x, lane = t & 31, wid = t >> 5;
    int j0 = blockIdx.x * 64;
    u32 dB = s2u(dsm);

    float acc[2][8][4];
#pragma unroll
    for (int mt = 0; mt < 2; mt++)
#pragma unroll
        for (int n = 0; n < 8; n++)
#pragma unroll
            for (int r = 0; r < 4; r++) acc[mt][n][r] = 0.f;

    // prologue: load chunk 0 into stage 0 (1280 CPA16)
    {
#pragma unroll
        for (int k = 0; k < 5; k++) {
            int e = t + k * 256;
            if (e < 1024) {
                int r = e >> 2, g = e & 3;
                CPA16(dB + r * 80 + g * 16,
                      (const char*)g_Vh + (size_t)r * NPH * 4 + g * 16);
            } else {
                int e2 = e - 1024;
                int r = e2 >> 2, g = e2 & 3;
                CPA16(dB + 20480 + r * 80 + g * 16,
                      (const char*)g_Wh + (size_t)(j0 + r) * NPH * 4 + g * 16);
            }
        }
        CPCOMMIT();
    }

    int arow = wid * 32 + (lane & 7) + ((lane >> 3) & 1) * 8;   // + mt*16
    int abo = (lane >> 4) * 16;
    int brow8 = lane & 7;
    int bbo = (lane >> 3) * 16;

    for (int ch = 0; ch < 288; ch++) {
        if (ch + 1 < 288) {
            size_t icp = (size_t)(ch + 1) * 16;       // u32-pair offset for 32 k
            u32 st = dB + ((ch + 1) & 1) * 25600;
#pragma unroll
            for (int k = 0; k < 5; k++) {
                int e = t + k * 256;
                if (e < 1024) {
                    int r = e >> 2, g = e & 3;
                    CPA16(st + r * 80 + g * 16,
                          (const char*)g_Vh + ((size_t)r * NPH + icp) * 4 + g * 16);
                } else {
                    int e2 = e - 1024;
                    int r = e2 >> 2, g = e2 & 3;
                    CPA16(st + 20480 + r * 80 + g * 16,
                          (const char*)g_Wh + ((size_t)(j0 + r) * NPH + icp) * 4 + g * 16);
                }
            }
            CPCOMMIT();
            CPWAIT1();
        } else {
            CPWAIT0();
        }
        __syncthreads();

        u32 base = dB + (ch & 1) * 25600;
        u32 vhB = base, whB = base + 20480;

        // A frags (V'): 2 m-tiles x 2 k-chunks of 16
        u32 a[2][2][4];
#pragma unroll
        for (int mt = 0; mt < 2; mt++) {
            int ar = arow + mt * 16;
            ldmx4(a[mt][0], vhB + ar * 80 + abo);        // k0-15
            ldmx4(a[mt][1], vhB + ar * 80 + 32 + abo);   // k16-31
        }
#pragma unroll
        for (int n = 0; n < 8; n++) {
            u32 bh[4];
            int br = n * 8 + brow8;
            ldmx4(bh, whB + br * 80 + bbo);              // k0-31
#pragma unroll
            for (int mt = 0; mt < 2; mt++) {
                mmab(acc[mt][n], a[mt][0], &bh[0]);
                mmab(acc[mt][n], a[mt][1], &bh[2]);
            }
        }
        __syncthreads();
    }

    // epilogue: Pt[c][j], coalesced in quads
#pragma unroll
    for (int mt = 0; mt < 2; mt++) {
#pragma unroll
        for (int n = 0; n < 8; n++) {
            int c = wid * 32 + mt * 16 + (lane >> 2);
            int col = j0 + n * 8 + 2 * (lane & 3);
            *(float2*)&g_Pt[(size_t)c * NP + col] =
                make_float2(acc[mt][n][0], acc[mt][n][1]);
            *(float2*)&g_Pt[(size_t)(c + 8) * NP + col] =
                make_float2(acc[mt][n][2], acc[mt][n][3]);
        }
    }
}

// ---------------- k4a: per-channel partial softmax stats (9 slices) ---------
__global__ void __launch_bounds__(256) k4a_part() {
    __shared__ float red[8];
    int c = blockIdx.x, sp = blockIdx.y;
    int t = threadIdx.x, lane = t & 31, w = t >> 5;
    const float* p = &g_Pt[(size_t)c * NP + sp * 1024];
    float v[4];
#pragma unroll
    for (int k = 0; k < 4; k++) v[k] = p[t + k * 256];
    float m = fmaxf(fmaxf(v[0], v[1]), fmaxf(v[2], v[3]));
    for (int off = 16; off; off >>= 1) m = fmaxf(m, __shfl_xor_sync(~0u, m, off));
    if (lane == 0) red[w] = m;
    __syncthreads();
    m = red[0];
#pragma unroll
    for (int k = 1; k < 8; k++) m = fmaxf(m, red[k]);
    float s = 0.f;
#pragma unroll
    for (int k = 0; k < 4; k++) s += __expf(v[k] - m);
    for (int off = 16; off; off >>= 1) s += __shfl_xor_sync(~0u, s, off);
    __syncthreads();
    if (lane == 0) red[w] = s;
    __syncthreads();
    if (t == 0) {
        s = 0.f;
#pragma unroll
        for (int k = 0; k < 8; k++) s += red[k];
        g_k4m[c][sp] = m;
        g_k4s[c][sp] = s;
    }
}

// ---------------- k4b: combine partials -------------------------------------
__global__ void __launch_bounds__(256) k4b_comb() {
    int c = threadIdx.x;
    float m = g_k4m[c][0];
#pragma unroll
    for (int k = 1; k < 9; k++) m = fmaxf(m, g_k4m[c][k]);
    float s = 0.f;
#pragma unroll
    for (int k = 0; k < 9; k++) s += g_k4s[c][k] * __expf(g_k4m[c][k] - m);
    g_cmax[c] = m;
    g_cisum[c] = 1.0f / s;
}

// ---------------- k5: out = softmax_w( x6 + x ) -----------------------------
__global__ void __launch_bounds__(96) k5_out(const float* __restrict__ x,
                                             float* __restrict__ out) {
    __shared__ float red[3];
    int b = blockIdx.x;
    int c = b / 96, h = b - c * 96;
    int t = threadIdx.x, lane = t & 31, w = t >> 5;
    size_t basei = (size_t)c * NP + h * 96;
    float v = __expf(g_Pt[basei + t] - g_cmax[c]) * g_cisum[c] + x[basei + t];
    float m = v;
    for (int off = 16; off; off >>= 1) m = fmaxf(m, __shfl_xor_sync(~0u, m, off));
    if (lane == 0) red[w] = m;
    __syncthreads();
    m = fmaxf(red[0], fmaxf(red[1], red[2]));
    float e = __expf(v - m);
    float s = e;
    for (int off = 16; off; off >>= 1) s += __shfl_xor_sync(~0u, s, off);
    __syncthreads();
    if (lane == 0) red[w] = s;
    __syncthreads();
    s = red[0] + red[1] + red[2];
    out[basei + t] = e / s;
}

// ---------------- launch ----------------------------------------------------
extern "C" void kernel_launch(void* const* d_in, const int* in_sizes, int n_in,
                              void* d_out, int out_size) {
    const float* x  = (const float*)d_in[0];
    const float* wc = (const float*)d_in[1];
    const float* bc = (const float*)d_in[2];
    float* out = (float*)d_out;

    cudaFuncSetAttribute(kS, cudaFuncAttributeMaxDynamicSharedMemorySize, 55296);
    cudaFuncSetAttribute(kPV, cudaFuncAttributeMaxDynamicSharedMemorySize, 51200);

    k0_init<<<1, 32>>>();
    k1_conv<<<72, 128>>>(x, wc, bc);
    kS<<<dim3(72, 4), 256, 55296>>>();
    kV<<<dim3(18, C), 256>>>(x);
    kPV<<<144, 256, 51200>>>();
    k4a_part<<<dim3(256, 9), 256>>>();
    k4b_comb<<<1, 256>>>();
    k5_out<<<24576, 96>>>(x, out);
}

// round 16
// speedup vs baseline: 1.1837x; 1.1837x over previous
#include <cuda_runtime.h>
#include <cuda_bf16.h>

#define NP 9216      // H*W
#define C  256
#define CO 32        // C/8
#define L2E 1.4426950408889634f
#define NPH 4608     // NP/2 (u32 pairs per row)

typedef unsigned long long ull;
typedef unsigned int u32;

// ---------------- device scratch (static; no dynamic allocation) -----------
__device__ __nv_bfloat16 g_Yt[(size_t)NP * 64]; // [i][o]: 0..31 hi, 32..63 lo
__device__ float g_Zp[4][NP];
__device__ u32   g_Wh[(size_t)NP * NPH];        // W = exp(S - M/2), bf16 pairs [j][i]
__device__ u32   g_Vh[(size_t)C * NPH];         // V' = x/Z, bf16 pairs [c][i]
__device__ float g_Pt[(size_t)C * NP];          // P [c][j]
__device__ float g_k4m[C][9];
__device__ float g_k4s[C][9];
__device__ float g_cmax[C];
__device__ float g_cisum[C];
__device__ int   g_Mbits;

// ---------------- PTX helpers ----------------------------------------------
__device__ __forceinline__ u32 s2u(const void* p) {
    u32 a;
    asm("{ .reg .u64 t; cvta.to.shared.u64 t, %1; cvt.u32.u64 %0, t; }"
        : "=r"(a) : "l"(p));
    return a;
}
__device__ __forceinline__ void mmab(float* d, const u32* a, const u32* b) {
    asm volatile(
        "mma.sync.aligned.m16n8k16.row.col.f32.bf16.bf16.f32 "
        "{%0,%1,%2,%3}, {%4,%5,%6,%7}, {%8,%9}, {%0,%1,%2,%3};"
        : "+f"(d[0]), "+f"(d[1]), "+f"(d[2]), "+f"(d[3])
        : "r"(a[0]), "r"(a[1]), "r"(a[2]), "r"(a[3]), "r"(b[0]), "r"(b[1]));
}
__device__ __forceinline__ void ldmx4(u32* r, u32 addr) {
    asm volatile("ldmatrix.sync.aligned.m8n8.x4.shared.b16 {%0,%1,%2,%3}, [%4];"
                 : "=r"(r[0]), "=r"(r[1]), "=r"(r[2]), "=r"(r[3]) : "r"(addr));
}
#define CPA16(s, g) asm volatile("cp.async.cg.shared.global [%0], [%1], 16;" :: "r"(s), "l"(g))
#define CPCOMMIT()  asm volatile("cp.async.commit_group;" ::: "memory")
#define CPWAIT0()   asm volatile("cp.async.wait_group 0;" ::: "memory")
#define CPWAIT1()   asm volatile("cp.async.wait_group 1;" ::: "memory")

// ---------------- k0 --------------------------------------------------------
__global__ void k0_init() { if (threadIdx.x == 0) g_Mbits = 0; }

// ---------------- k1: conv -> Yt (bf16 hi/lo, i = w*96+h), M ---------------
__global__ void __launch_bounds__(128) k1_conv(const float* __restrict__ x,
                                               const float* __restrict__ wc,
                                               const float* __restrict__ bc) {
    __shared__ float ws[C * CO];
    __shared__ float bs[CO];
    int t = threadIdx.x;
    for (int idx = t; idx < C * CO; idx += 128)
        ws[idx] = wc[(idx & 31) * C + (idx >> 5)];
    if (t < CO) bs[t] = bc[t];
    __syncthreads();

    int pos = blockIdx.x * 128 + t;                  // h*96 + w
    float acc[CO];
#pragma unroll
    for (int o = 0; o < CO; o++) acc[o] = bs[o];
#pragma unroll 4
    for (int c = 0; c < C; c++) {
        float xv = x[c * NP + pos];
        const float4* wp = (const float4*)&ws[c * CO];
#pragma unroll
        for (int q = 0; q < 8; q++) {
            float4 w4 = wp[q];
            acc[q * 4 + 0] += w4.x * xv;
            acc[q * 4 + 1] += w4.y * xv;
            acc[q * 4 + 2] += w4.z * xv;
            acc[q * 4 + 3] += w4.w * xv;
        }
    }
    int h = pos / 96, w = pos - h * 96;
    int i = w * 96 + h;                              // transposed spatial index
    float ss = 0.0f;
#pragma unroll
    for (int o = 0; o < CO; o++) {
        float a = acc[o];
        ss += a * a;
        __nv_bfloat16 hb = __float2bfloat16(a);
        g_Yt[(size_t)i * 64 + o] = hb;
        g_Yt[(size_t)i * 64 + 32 + o] = __float2bfloat16(a - __bfloat162float(hb));
    }
    atomicMax(&g_Mbits, __float_as_int(ss));
}

// ---------------- kS: S tiles (mma 3-term), W = exp2(S*l2e - M/2*l2e) ------
// grid (72, 4): j-tile 128, i-quarter of 18 i-tiles (128 each). 256 thr, 2/SM.
// dyn smem: A[0,18432) B0[18432,36864) B1[36864,55296)
__global__ void __launch_bounds__(256, 2) kS() {
    extern __shared__ __align__(16) char dsm[];
    int t = threadIdx.x, lane = t & 31, wid = t >> 5;
    int j0 = blockIdx.x * 128, q = blockIdx.y;
    u32 aB = s2u(dsm);
    float mh = 0.5f * __int_as_float(g_Mbits) * L2E;

    // stage A (j-tile) + B(0) in one group
#pragma unroll
    for (int k = 0; k < 4; k++) {
        int idx = t + k * 256;
        int row = idx >> 3, g = idx & 7;
        CPA16(aB + row * 144 + g * 16,
              (const char*)g_Yt + (size_t)(j0 + row) * 128 + g * 16);
    }
    int ib0 = q * 2304;
#pragma unroll
    for (int k = 0; k < 4; k++) {
        int idx = t + k * 256;
        int row = idx >> 3, g = idx & 7;
        CPA16(aB + 18432 + row * 144 + g * 16,
              (const char*)g_Yt + (size_t)(ib0 + row) * 128 + g * 16);
    }
    CPCOMMIT();
    CPWAIT0();
    __syncthreads();

    // A fragments, resident in regs
    u32 af[4][4];
    {
        int arow = wid * 16 + (lane & 7) + ((lane >> 3) & 1) * 8;
        int abo = (lane >> 4) * 16;
#pragma unroll
        for (int kc = 0; kc < 4; kc++)
            ldmx4(af[kc], aB + arow * 144 + kc * 32 + abo);
    }

    int r0 = wid * 16 + (lane >> 2), r1 = r0 + 8;
    float z0 = 0.f, z1 = 0.f;

    for (int it = 0; it < 18; it++) {
        if (it + 1 < 18) {
            int i1 = q * 2304 + (it + 1) * 128;
            u32 st = aB + 18432 + ((it + 1) & 1) * 18432;
#pragma unroll
            for (int k = 0; k < 4; k++) {
                int idx = t + k * 256;
                int row = idx >> 3, g = idx & 7;
                CPA16(st + row * 144 + g * 16,
                      (const char*)g_Yt + (size_t)(i1 + row) * 128 + g * 16);
            }
            CPCOMMIT();
            CPWAIT1();
        } else {
            CPWAIT0();
        }
        __syncthreads();

        u32 bB = aB + 18432 + (it & 1) * 18432;
        int i0 = q * 2304 + it * 128;

        float acc[16][4];
#pragma unroll
        for (int n = 0; n < 16; n++)
#pragma unroll
            for (int r = 0; r < 4; r++) acc[n][r] = 0.f;

#pragma unroll
        for (int n = 0; n < 16; n++) {
            u32 bh[4], bl[4];
            int brow = n * 8 + (lane & 7);
            int bbo = (lane >> 3) * 16;
            ldmx4(bh, bB + brow * 144 + bbo);
            ldmx4(bl, bB + brow * 144 + 64 + bbo);
            mmab(acc[n], af[0], &bh[0]);             // hh
            mmab(acc[n], af[1], &bh[2]);
            mmab(acc[n], af[0], &bl[0]);             // hl
            mmab(acc[n], af[1], &bl[2]);
            mmab(acc[n], af[2], &bh[0]);             // lh
            mmab(acc[n], af[3], &bh[2]);
        }

        // epilogue: t = exp2(S*l2e - mh); z += t; store bf16 W
#pragma unroll
        for (int n = 0; n < 16; n++) {
            int cc = n * 8 + 2 * (lane & 3);
            float t0 = exp2f(fmaf(acc[n][0], L2E, -mh));
            float t1 = exp2f(fmaf(acc[n][1], L2E, -mh));
            float t2 = exp2f(fmaf(acc[n][2], L2E, -mh));
            float t3 = exp2f(fmaf(acc[n][3], L2E, -mh));
            z0 += t0 + t1;
            z1 += t2 + t3;
            __nv_bfloat162 h0 = __floats2bfloat162_rn(t0, t1);
            __nv_bfloat162 h1 = __floats2bfloat162_rn(t2, t3);
            size_t ip = (size_t)(i0 + cc) >> 1;
            g_Wh[(size_t)(j0 + r0) * NPH + ip] = *(u32*)&h0;
            g_Wh[(size_t)(j0 + r1) * NPH + ip] = *(u32*)&h1;
        }
        __syncthreads();
    }
    z0 += __shfl_xor_sync(~0u, z0, 1); z0 += __shfl_xor_sync(~0u, z0, 2);
    z1 += __shfl_xor_sync(~0u, z1, 1); z1 += __shfl_xor_sync(~0u, z1, 2);
    if ((lane & 3) == 0) {
        g_Zp[q][j0 + r0] = z0;
        g_Zp[q][j0 + r1] = z1;
    }
}

// ---------------- kV: V'[c][i] = x[c][i]/Z[i], bf16 (invZ inline) -----------
__global__ void __launch_bounds__(256) kV(const float* __restrict__ x) {
    int c = blockIdx.y;
    int i = blockIdx.x * 256 + threadIdx.x;          // pair index < 4608
    float2 xv = *(const float2*)&x[(size_t)c * NP + 2 * i];
    float z0 = ((g_Zp[0][2 * i] + g_Zp[1][2 * i]) + g_Zp[2][2 * i]) + g_Zp[3][2 * i];
    float z1 = ((g_Zp[0][2 * i + 1] + g_Zp[1][2 * i + 1]) + g_Zp[2][2 * i + 1]) + g_Zp[3][2 * i + 1];
    __nv_bfloat162 hh = __floats2bfloat162_rn(xv.x / z0, xv.y / z1);
    g_Vh[(size_t)c * NPH + i] = *(u32*)&hh;
}

// ---------------- kPV: Pt[c][j] = sum_i V'[c][i]*W[j][i], single-term -------
// grid (144): j-tile 64, m = all 256 c. 256 thr, warp = 32-c strip. K-chunk 64.
// dyn smem stage (46080): Vh[0,36864) Wh[36864,46080); x2 = 92160
__global__ void __launch_bounds__(256) kPV() {
    extern __shared__ __align__(16) char dsm[];
    int t = threadIdx.x, lane = t & 31, wid = t >> 5;
    int j0 = blockIdx.x * 64;
    u32 dB = s2u(dsm);

    float acc[2][8][4];
#pragma unroll
    for (int mt = 0; mt < 2; mt++)
#pragma unroll
        for (int n = 0; n < 8; n++)
#pragma unroll
            for (int r = 0; r < 4; r++) acc[mt][n][r] = 0.f;

    // prologue: load chunk 0 into stage 0
    {
        size_t icp = 0;
#pragma unroll
        for (int k = 0; k < 10; k++) {
            int e = t + k * 256;
            if (e < 2048) {
                int r = e >> 3, g = e & 7;
                CPA16(dB + r * 144 + g * 16,
                      (const char*)g_Vh + ((size_t)r * NPH + icp) * 4 + g * 16);
            } else {
                int e2 = e - 2048;
                int r = e2 >> 3, g = e2 & 7;
                CPA16(dB + 36864 + r * 144 + g * 16,
                      (const char*)g_Wh + ((size_t)(j0 + r) * NPH + icp) * 4 + g * 16);
            }
        }
        CPCOMMIT();
    }

    int arow = wid * 32 + (lane & 7) + ((lane >> 3) & 1) * 8;   // + mt*16
    int abo = (lane >> 4) * 16;
    int brow8 = lane & 7;
    int bbo = (lane >> 3) * 16;

    for (int ch = 0; ch < 144; ch++) {
        if (ch + 1 < 144) {
            size_t icp = (size_t)(ch + 1) * 32;       // u32-pair offset for 64 k
            u32 st = dB + ((ch + 1) & 1) * 46080;
#pragma unroll
            for (int k = 0; k < 10; k++) {
                int e = t + k * 256;
                if (e < 2048) {
                    int r = e >> 3, g = e & 7;
                    CPA16(st + r * 144 + g * 16,
                          (const char*)g_Vh + ((size_t)r * NPH + icp) * 4 + g * 16);
                } else {
                    int e2 = e - 2048;
                    int r = e2 >> 3, g = e2 & 7;
                    CPA16(st + 36864 + r * 144 + g * 16,
                          (const char*)g_Wh + ((size_t)(j0 + r) * NPH + icp) * 4 + g * 16);
                }
            }
            CPCOMMIT();
            CPWAIT1();
        } else {
            CPWAIT0();
        }
        __syncthreads();

        u32 base = dB + (ch & 1) * 46080;
        u32 vhB = base, whB = base + 36864;

        // A frags (V'): 2 m-tiles x 4 k-chunks of 16
        u32 a[2][4][4];
#pragma unroll
        for (int mt = 0; mt < 2; mt++) {
            int ar = arow + mt * 16;
#pragma unroll
            for (int kc = 0; kc < 4; kc++)
                ldmx4(a[mt][kc], vhB + ar * 144 + kc * 32 + abo);
        }
#pragma unroll
        for (int n = 0; n < 8; n++) {
            u32 bh[4], bh2[4];
            int br = n * 8 + brow8;
            ldmx4(bh,  whB + br * 144 + bbo);        // k0-31
            ldmx4(bh2, whB + br * 144 + 64 + bbo);   // k32-63
#pragma unroll
            for (int mt = 0; mt < 2; mt++) {
                mmab(acc[mt][n], a[mt][0], &bh[0]);
                mmab(acc[mt][n], a[mt][1], &bh[2]);
                mmab(acc[mt][n], a[mt][2], &bh2[0]);
                mmab(acc[mt][n], a[mt][3], &bh2[2]);
            }
        }
        __syncthreads();
    }

    // epilogue: Pt[c][j], coalesced in quads
#pragma unroll
    for (int mt = 0; mt < 2; mt++) {
#pragma unroll
        for (int n = 0; n < 8; n++) {
            int c = wid * 32 + mt * 16 + (lane >> 2);
            int col = j0 + n * 8 + 2 * (lane & 3);
            *(float2*)&g_Pt[(size_t)c * NP + col] =
                make_float2(acc[mt][n][0], acc[mt][n][1]);
            *(float2*)&g_Pt[(size_t)(c + 8) * NP + col] =
                make_float2(acc[mt][n][2], acc[mt][n][3]);
        }
    }
}

// ---------------- k4a: per-channel partial softmax stats (9 slices) ---------
__global__ void __launch_bounds__(256) k4a_part() {
    __shared__ float red[8];
    int c = blockIdx.x, sp = blockIdx.y;
    int t = threadIdx.x, lane = t & 31, w = t >> 5;
    const float* p = &g_Pt[(size_t)c * NP + sp * 1024];
    float v[4];
#pragma unroll
    for (int k = 0; k < 4; k++) v[k] = p[t + k * 256];
    float m = fmaxf(fmaxf(v[0], v[1]), fmaxf(v[2], v[3]));
    for (int off = 16; off; off >>= 1) m = fmaxf(m, __shfl_xor_sync(~0u, m, off));
    if (lane == 0) red[w] = m;
    __syncthreads();
    m = red[0];
#pragma unroll
    for (int k = 1; k < 8; k++) m = fmaxf(m, red[k]);
    float s = 0.f;
#pragma unroll
    for (int k = 0; k < 4; k++) s += __expf(v[k] - m);
    for (int off = 16; off; off >>= 1) s += __shfl_xor_sync(~0u, s, off);
    __syncthreads();
    if (lane == 0) red[w] = s;
    __syncthreads();
    if (t == 0) {
        s = 0.f;
#pragma unroll
        for (int k = 0; k < 8; k++) s += red[k];
        g_k4m[c][sp] = m;
        g_k4s[c][sp] = s;
    }
}

// ---------------- k4b: combine partials -------------------------------------
__global__ void __launch_bounds__(256) k4b_comb() {
    int c = threadIdx.x;
    float m = g_k4m[c][0];
#pragma unroll
    for (int k = 1; k < 9; k++) m = fmaxf(m, g_k4m[c][k]);
    float s = 0.f;
#pragma unroll
    for (int k = 0; k < 9; k++) s += g_k4s[c][k] * __expf(g_k4m[c][k] - m);
    g_cmax[c] = m;
    g_cisum[c] = 1.0f / s;
}

// ---------------- k5: out = softmax_w( x6 + x ) -----------------------------
__global__ void __launch_bounds__(96) k5_out(const float* __restrict__ x,
                                             float* __restrict__ out) {
    __shared__ float red[3];
    int b = blockIdx.x;
    int c = b / 96, h = b - c * 96;
    int t = threadIdx.x, lane = t & 31, w = t >> 5;
    size_t basei = (size_t)c * NP + h * 96;
    float v = __expf(g_Pt[basei + t] - g_cmax[c]) * g_cisum[c] + x[basei + t];
    float m = v;
    for (int off = 16; off; off >>= 1) m = fmaxf(m, __shfl_xor_sync(~0u, m, off));
    if (lane == 0) red[w] = m;
    __syncthreads();
    m = fmaxf(red[0], fmaxf(red[1], red[2]));
    float e = __expf(v - m);
    float s = e;
    for (int off = 16; off; off >>= 1) s += __shfl_xor_sync(~0u, s, off);
    __syncthreads();
    if (lane == 0) red[w] = s;
    __syncthreads();
    s = red[0] + red[1] + red[2];
    out[basei + t] = e / s;
}

// ---------------- launch ----------------------------------------------------
extern "C" void kernel_launch(void* const* d_in, const int* in_sizes, int n_in,
                              void* d_out, int out_size) {
    const float* x  = (const float*)d_in[0];
    const float* wc = (const float*)d_in[1];
    const float* bc = (const float*)d_in[2];
    float* out = (float*)d_out;

    cudaFuncSetAttribute(kS, cudaFuncAttributeMaxDynamicSharedMemorySize, 55296);
    cudaFuncSetAttribute(kPV, cudaFuncAttributeMaxDynamicSharedMemorySize, 92160);

    k0_init<<<1, 32>>>();
    k1_conv<<<72, 128>>>(x, wc, bc);
    kS<<<dim3(72, 4), 256, 55296>>>();
    kV<<<dim3(18, C), 256>>>(x);
    kPV<<<144, 256, 92160>>>();
    k4a_part<<<dim3(256, 9), 256>>>();
    k4b_comb<<<1, 256>>>();
    k5_out<<<24576, 96>>>(x, out);
}